// round 10
// baseline (speedup 1.0000x reference)
#include <cuda_runtime.h>
#include <math.h>
#include <stdint.h>

// ---------------------------------------------------------------------------
// mLSTM cell, B=128, D_IN=1024, H=1024  (SIMT + FFMA2 + cp.async pipeline;
// harness ptxas = sm_103 plain, tcgen05 unavailable)
// output: concat[ h_new (128*1024), C_new (128*1024*1024), n_new (128*1024) ]
// ---------------------------------------------------------------------------

#define Bsz   128
#define Hdim  1024
#define NQKV  3072   // dead 'g' quarter of proj is skipped
#define KSPLIT 12
#define OUTMN (Bsz * NQKV)   // 393216

__device__ float g_qkv[Bsz * NQKV];        // [b][ q | k | v ]
__device__ float g_ifo[Bsz * NQKV];        // [b][ i | f | o ]
__device__ float g_part[KSPLIT * OUTMN];   // split-K partials (reused K1/K2)
__device__ float g_hpart[8 * Bsz * Hdim];  // per-h-tile h_lin partials
__device__ float g_denom[Bsz];

// ---- packed f32x2 helpers ----
__device__ __forceinline__ unsigned long long pack_dup(float a) {
    unsigned long long r;
    uint32_t au = __float_as_uint(a);
    asm("mov.b64 %0, {%1, %1};" : "=l"(r) : "r"(au));
    return r;
}
__device__ __forceinline__ void fma2(unsigned long long& d,
                                     unsigned long long a,
                                     unsigned long long b) {
    asm("fma.rn.f32x2 %0, %1, %2, %0;" : "+l"(d) : "l"(a), "l"(b));
}
__device__ __forceinline__ float2 unpack2(unsigned long long v) {
    uint32_t lo, hi;
    asm("mov.b64 {%0, %1}, %2;" : "=r"(lo), "=r"(hi) : "l"(v));
    return make_float2(__uint_as_float(lo), __uint_as_float(hi));
}
__device__ __forceinline__ uint32_t smem_u32(const void* p) {
    uint32_t a;
    asm("{ .reg .u64 t; cvta.to.shared.u64 t, %1; cvt.u32.u64 %0, t; }"
        : "=r"(a) : "l"(p));
    return a;
}
__device__ __forceinline__ void cp_async16(uint32_t dst, const float* src) {
    asm volatile("cp.async.cg.shared.global [%0], [%1], 16;"
                 :: "r"(dst), "l"(src));
}

// ---------------------------------------------------------------------------
// Split-K GEMM mainloop: partial[kz] = A[128, k-chunk] * W[k-chunk, 3072]
// MODE 0: A = x (arg, lda=1024), ldw = 4096 ; MODE 1: A = v slice of g_qkv
// BM=128 BN=128 BK=16, 256 threads, 8x8 per-thread FFMA2 tile.
// W streamed via 4-stage cp.async ring; A register double-buffered.
// grid (24, 1, 12) = 288 blocks = 2/SM (launch_bounds(256,2)).
// K split: 64 BK-iters as 6,6,6,6,5x8.
// ---------------------------------------------------------------------------
template <int MODE>
__global__ __launch_bounds__(256, 2) void gemm_main_kernel(
    const float* __restrict__ Aext, const float* __restrict__ W)
{
    const float* __restrict__ A = (MODE == 0) ? Aext : (const float*)(g_qkv + 2048);
    const int lda = (MODE == 0) ? 1024 : NQKV;
    const int ldw = (MODE == 0) ? 4096 : 3072;

    __shared__ float As[2][16][128];   // [buf][kk][m] transposed (16 KB)
    __shared__ float Bs[4][16][128];   // [stage][kk][n] cp.async ring (32 KB)

    const int tid = threadIdx.x;
    const int bn = blockIdx.x * 128;
    const int kz = blockIdx.z;

    // A loads: 128 rows x 16 k = 512 float4, 2 per thread
    const int aRow = tid >> 1;           // 0..127
    const int aK   = (tid & 1) * 8;      // 0 or 8 (two float4: aK, aK+4)
    // B loads: 16 rows(k) x 128 cols, 2x16B per thread
    const int bRow = tid >> 4;           // 0..15
    const int bCol = (tid & 15) * 8;

    // compute: ty 0..15 -> 8 M rows, tx 0..15 -> 8 N cols (4 f32x2 pairs)
    const int mrow = (tid >> 4) * 8;
    const int ncol = (tid & 15) * 8;

    unsigned long long acc2[8][4];
#pragma unroll
    for (int r = 0; r < 8; r++)
#pragma unroll
        for (int c = 0; c < 4; c++) acc2[r][c] = 0ull;

    // K split: 64 BK-iters as 6,6,6,6 then 5x8
    const int it0   = (kz < 4) ? 6 * kz : 24 + 5 * (kz - 4);
    const int iters = (kz < 4) ? 6 : 5;

    const uint32_t bsDst = smem_u32(&Bs[0][0][0]) + (uint32_t)(bRow * 128 + bCol) * 4;

    // ---- prologue: A tile 0 via regs->smem; B stages 0..2 via cp.async ----
    {
        const int k0 = it0 * 16;
        float4 av0 = *(const float4*)(A + (size_t)aRow * lda + k0 + aK);
        float4 av1 = *(const float4*)(A + (size_t)aRow * lda + k0 + aK + 4);
        As[0][aK + 0][aRow] = av0.x; As[0][aK + 1][aRow] = av0.y;
        As[0][aK + 2][aRow] = av0.z; As[0][aK + 3][aRow] = av0.w;
        As[0][aK + 4][aRow] = av1.x; As[0][aK + 5][aRow] = av1.y;
        As[0][aK + 6][aRow] = av1.z; As[0][aK + 7][aRow] = av1.w;
    }
#pragma unroll
    for (int s = 0; s < 3; s++) {
        if (s < iters) {
            const int k0 = (it0 + s) * 16;
            const float* src = W + (size_t)(k0 + bRow) * ldw + bn + bCol;
            uint32_t dst = bsDst + (uint32_t)(s * 16 * 128 * 4);
            cp_async16(dst, src);
            cp_async16(dst + 16, src + 4);
        }
        asm volatile("cp.async.commit_group;");
    }

    int cur = 0;
    for (int it = 0; it < iters; it++) {
        const bool hasA = (it + 1 < iters);
        float4 av0, av1;
        if (hasA) {
            const int k0 = (it0 + it + 1) * 16;
            av0 = *(const float4*)(A + (size_t)aRow * lda + k0 + aK);
            av1 = *(const float4*)(A + (size_t)aRow * lda + k0 + aK + 4);
        }

        asm volatile("cp.async.wait_group 2;");
        __syncthreads();

        const int st = it & 3;
#pragma unroll
        for (int kk = 0; kk < 16; kk++) {
            float4 a0 = *(const float4*)&As[cur][kk][mrow];
            float4 a1 = *(const float4*)&As[cur][kk][mrow + 4];
            ulonglong2 bb0 = *(const ulonglong2*)&Bs[st][kk][ncol];
            ulonglong2 bb1 = *(const ulonglong2*)&Bs[st][kk][ncol + 4];
            unsigned long long a2[8];
            a2[0] = pack_dup(a0.x); a2[1] = pack_dup(a0.y);
            a2[2] = pack_dup(a0.z); a2[3] = pack_dup(a0.w);
            a2[4] = pack_dup(a1.x); a2[5] = pack_dup(a1.y);
            a2[6] = pack_dup(a1.z); a2[7] = pack_dup(a1.w);
#pragma unroll
            for (int r = 0; r < 8; r++) {
                fma2(acc2[r][0], a2[r], bb0.x);
                fma2(acc2[r][1], a2[r], bb0.y);
                fma2(acc2[r][2], a2[r], bb1.x);
                fma2(acc2[r][3], a2[r], bb1.y);
            }
        }

        if (hasA) {
            const int nxt = cur ^ 1;
            As[nxt][aK + 0][aRow] = av0.x; As[nxt][aK + 1][aRow] = av0.y;
            As[nxt][aK + 2][aRow] = av0.z; As[nxt][aK + 3][aRow] = av0.w;
            As[nxt][aK + 4][aRow] = av1.x; As[nxt][aK + 5][aRow] = av1.y;
            As[nxt][aK + 6][aRow] = av1.z; As[nxt][aK + 7][aRow] = av1.w;
            cur = nxt;
        }
        if (it + 3 < iters) {
            const int k0 = (it0 + it + 3) * 16;
            const float* src = W + (size_t)(k0 + bRow) * ldw + bn + bCol;
            uint32_t dst = bsDst + (uint32_t)(((it + 3) & 3) * 16 * 128 * 4);
            cp_async16(dst, src);
            cp_async16(dst + 16, src + 4);
        }
        asm volatile("cp.async.commit_group;");   // possibly empty group
    }

    float* __restrict__ part = g_part + (size_t)kz * OUTMN;
#pragma unroll
    for (int r = 0; r < 8; r++) {
        int m = mrow + r;
        float2 p0 = unpack2(acc2[r][0]);
        float2 p1 = unpack2(acc2[r][1]);
        float2 p2 = unpack2(acc2[r][2]);
        float2 p3 = unpack2(acc2[r][3]);
        *(float4*)(part + (size_t)m * NQKV + bn + ncol) =
            make_float4(p0.x, p0.y, p1.x, p1.y);
        *(float4*)(part + (size_t)m * NQKV + bn + ncol + 4) =
            make_float4(p2.x, p2.y, p3.x, p3.y);
    }
}

// ---------------------------------------------------------------------------
// GEMM epilogue: sum KSPLIT partials + bias + activation -> g_qkv / g_ifo
// MODE 0: tanh for n<2048, identity for v ; MODE 1: sigmoid
// ---------------------------------------------------------------------------
template <int MODE>
__global__ __launch_bounds__(256) void gemm_epi_kernel(const float* __restrict__ bias)
{
    const int idx = blockIdx.x * 256 + threadIdx.x;   // 0 .. OUTMN-1
    const int nn = idx % NQKV;
    float v = bias[nn];
#pragma unroll
    for (int p = 0; p < KSPLIT; p++) v += g_part[(size_t)p * OUTMN + idx];
    if (MODE == 0) {
        if (nn < 2048) v = tanhf(v);
        g_qkv[idx] = v;
    } else {
        g_ifo[idx] = 1.0f / (1.0f + expf(-v));
    }
}

// ---------------------------------------------------------------------------
// n_new = f*n + i*k ; denom[b] = max(sum_d q*n_new, 1e-6)
// ---------------------------------------------------------------------------
__global__ __launch_bounds__(256) void nnew_denom_kernel(
    const float* __restrict__ n_in, float* __restrict__ out_n)
{
    const int b = blockIdx.x;
    const int tid = threadIdx.x;
    __shared__ float red[256];

    float psum = 0.f;
#pragma unroll
    for (int d = tid; d < Hdim; d += 256) {
        float iv = g_ifo[b * NQKV + d];
        float fv = g_ifo[b * NQKV + 1024 + d];
        float kv = g_qkv[b * NQKV + 1024 + d];
        float qv = g_qkv[b * NQKV + d];
        float nn = fv * n_in[b * Hdim + d] + iv * kv;
        out_n[b * Hdim + d] = nn;
        psum += qv * nn;
    }
    red[tid] = psum;
    __syncthreads();
#pragma unroll
    for (int s = 128; s > 0; s >>= 1) {
        if (tid < s) red[tid] += red[tid + s];
        __syncthreads();
    }
    if (tid == 0) g_denom[b] = fmaxf(red[0], 1e-6f);
}

// ---------------------------------------------------------------------------
// K3: streaming C update fused with h_lin reduction (single pass over C).
// grid = 128 b * 8 htiles = 1024 blocks, 256 threads. Round-6 form.
// ---------------------------------------------------------------------------
#define TILE_H 128

__global__ __launch_bounds__(256) void update_C_kernel(
    const float* __restrict__ C, float* __restrict__ outC)
{
    const int bid = blockIdx.x;
    const int b  = bid >> 3;
    const int ht = bid & 7;
    const int tid = threadIdx.x;

    __shared__ float qs[TILE_H], fs[TILE_H], iks[TILE_H];
    if (tid < TILE_H) {
        int h = ht * TILE_H + tid;
        qs[tid]  = g_qkv[b * NQKV + h];
        float kv = g_qkv[b * NQKV + 1024 + h];
        float iv = g_ifo[b * NQKV + h];
        fs[tid]  = g_ifo[b * NQKV + 1024 + h];
        iks[tid] = iv * kv;
    }
    __syncthreads();

    const int d = tid * 4;
    const float4 v4 = *(const float4*)(g_qkv + b * NQKV + 2048 + d);

    const size_t base = (size_t)b * Hdim * Hdim + (size_t)ht * TILE_H * Hdim + d;
    const float* __restrict__ src = C + base;
    float* __restrict__ dst = outC + base;

    float4 acc = make_float4(0.f, 0.f, 0.f, 0.f);

#pragma unroll 8
    for (int j = 0; j < TILE_H; j++) {
        float4 c4 = __ldcs((const float4*)(src + (size_t)j * Hdim));
        const float fv = fs[j], ik = iks[j], qv = qs[j];
        float4 cn;
        cn.x = fmaf(fv, c4.x, ik * v4.x);
        cn.y = fmaf(fv, c4.y, ik * v4.y);
        cn.z = fmaf(fv, c4.z, ik * v4.z);
        cn.w = fmaf(fv, c4.w, ik * v4.w);
        __stcs((float4*)(dst + (size_t)j * Hdim), cn);
        acc.x = fmaf(qv, cn.x, acc.x);
        acc.y = fmaf(qv, cn.y, acc.y);
        acc.z = fmaf(qv, cn.z, acc.z);
        acc.w = fmaf(qv, cn.w, acc.w);
    }

    *(float4*)(g_hpart + ht * (Bsz * Hdim) + (b << 10) + d) = acc;
}

// ---------------------------------------------------------------------------
// K4: h_new = o * (sum_ht h_lin_part) / denom
// ---------------------------------------------------------------------------
__global__ __launch_bounds__(256) void finalize_h_kernel(float* __restrict__ out_h)
{
    const int idx = blockIdx.x * 256 + threadIdx.x;   // 131072 total
    const int b = idx >> 10;
    const int d = idx & 1023;
    float hl = 0.f;
#pragma unroll
    for (int p = 0; p < 8; p++) hl += g_hpart[p * (Bsz * Hdim) + (b << 10) + d];
    out_h[idx] = g_ifo[b * NQKV + 2048 + d] * hl / g_denom[b];
}

// ---------------------------------------------------------------------------
extern "C" void kernel_launch(void* const* d_in, const int* in_sizes, int n_in,
                              void* d_out, int out_size)
{
    // order-agnostic input resolution by element count
    const float *x = 0, *C = 0, *n_in_p = 0;
    const float *W_proj = 0, *b_proj = 0, *W_gates = 0, *b_gates = 0;

    const float* trio[3] = {0, 0, 0};
    int ntrio = 0;
    for (int idx = 0; idx < n_in; idx++) {
        const float* p = (const float*)d_in[idx];
        switch (in_sizes[idx]) {
            case 134217728: C       = p; break;
            case 4194304:   W_proj  = p; break;
            case 3145728:   W_gates = p; break;
            case 4096:      b_proj  = p; break;
            case 3072:      b_gates = p; break;
            case 131072:    if (ntrio < 3) trio[ntrio++] = p; break;
            default: break;
        }
    }
    n_in_p = trio[1];
    if (in_sizes[0] == 131072) x = trio[0];
    else                       x = trio[2];

    float* out   = (float*)d_out;
    float* out_h = out;
    float* out_C = out + Bsz * Hdim;
    float* out_n = out + Bsz * Hdim + (size_t)Bsz * Hdim * Hdim;

    dim3 ggrid(NQKV / 128, 1, KSPLIT);   // (24, 1, 12) = 288 blocks
    // K1: proj GEMM -> partials -> epi(tanh/identity) -> g_qkv
    gemm_main_kernel<0><<<ggrid, 256>>>(x, W_proj);
    gemm_epi_kernel<0><<<OUTMN / 256, 256>>>(b_proj);
    // K2: gates GEMM (A = v slice, resolved in-device) -> epi(sigmoid) -> g_ifo
    gemm_main_kernel<1><<<ggrid, 256>>>(nullptr, W_gates);
    gemm_epi_kernel<1><<<OUTMN / 256, 256>>>(b_gates);
    // n_new + denom
    nnew_denom_kernel<<<Bsz, 256>>>(n_in_p, out_n);
    // C update + fused h_lin reduction (single pass over C)
    update_C_kernel<<<Bsz * 8, 256>>>(C, out_C);
    // finalize h
    finalize_h_kernel<<<(Bsz * Hdim) / 256, 256>>>(out_h);
}

// round 11
// speedup vs baseline: 1.0188x; 1.0188x over previous
#include <cuda_runtime.h>
#include <math.h>
#include <stdint.h>

// ---------------------------------------------------------------------------
// mLSTM cell, B=128, D_IN=1024, H=1024  (SIMT + FFMA2;
// harness ptxas = sm_103 plain, tcgen05 unavailable)
// output: concat[ h_new (128*1024), C_new (128*1024*1024), n_new (128*1024) ]
// ---------------------------------------------------------------------------

#define Bsz   128
#define Hdim  1024
#define NQKV  3072   // dead 'g' quarter of proj is skipped
#define KSPLIT 6
#define OUTMN (Bsz * NQKV)   // 393216

__device__ float g_qkv[Bsz * NQKV];        // [b][ q | k | v ]
__device__ float g_ifo[Bsz * NQKV];        // [b][ i | f | o ]
__device__ float g_part[KSPLIT * OUTMN];   // split-K partials (reused K1/K2)
__device__ float g_hpart[8 * Bsz * Hdim];  // per-h-tile h_lin partials
__device__ float g_denom[Bsz];

// ---- packed f32x2 helpers ----
__device__ __forceinline__ unsigned long long pack_dup(float a) {
    unsigned long long r;
    uint32_t au = __float_as_uint(a);
    asm("mov.b64 %0, {%1, %1};" : "=l"(r) : "r"(au));
    return r;
}
__device__ __forceinline__ void fma2(unsigned long long& d,
                                     unsigned long long a,
                                     unsigned long long b) {
    asm("fma.rn.f32x2 %0, %1, %2, %0;" : "+l"(d) : "l"(a), "l"(b));
}
__device__ __forceinline__ float2 unpack2(unsigned long long v) {
    uint32_t lo, hi;
    asm("mov.b64 {%0, %1}, %2;" : "=r"(lo), "=r"(hi) : "l"(v));
    return make_float2(__uint_as_float(lo), __uint_as_float(hi));
}

// ---------------------------------------------------------------------------
// Split-K GEMM mainloop (round-9 best form): BM=128 BN=128 BK=16,
// 256 threads, 8x8 per-thread FFMA2 tile, double-buffered smem.
// grid (24, 1, 6) = 144 blocks; K split 11,11,11,11,10,10.
// ---------------------------------------------------------------------------
template <int MODE>
__global__ __launch_bounds__(256) void gemm_main_kernel(
    const float* __restrict__ Aext, const float* __restrict__ W)
{
    const float* __restrict__ A = (MODE == 0) ? Aext : (const float*)(g_qkv + 2048);
    const int lda = (MODE == 0) ? 1024 : NQKV;
    const int ldw = (MODE == 0) ? 4096 : 3072;

    __shared__ float As[2][16][132];   // [buf][kk][m] transposed, padded
    __shared__ float Bs[2][16][128];   // [buf][kk][n]

    const int tid = threadIdx.x;
    const int bn = blockIdx.x * 128;
    const int kz = blockIdx.z;

    const int aRow = tid >> 1;           // 0..127
    const int aK   = (tid & 1) * 8;
    const int bRow = tid >> 4;           // 0..15
    const int bCol = (tid & 15) * 8;

    const int mrow = (tid >> 4) * 8;
    const int ncol = (tid & 15) * 8;

    unsigned long long acc2[8][4];
#pragma unroll
    for (int r = 0; r < 8; r++)
#pragma unroll
        for (int c = 0; c < 4; c++) acc2[r][c] = 0ull;

    const int it0   = kz * 10 + (kz < 4 ? kz : 4);
    const int iters = (kz < 4) ? 11 : 10;

    {
        const int k0 = it0 * 16;
        float4 av0 = *(const float4*)(A + (size_t)aRow * lda + k0 + aK);
        float4 av1 = *(const float4*)(A + (size_t)aRow * lda + k0 + aK + 4);
        As[0][aK + 0][aRow] = av0.x; As[0][aK + 1][aRow] = av0.y;
        As[0][aK + 2][aRow] = av0.z; As[0][aK + 3][aRow] = av0.w;
        As[0][aK + 4][aRow] = av1.x; As[0][aK + 5][aRow] = av1.y;
        As[0][aK + 6][aRow] = av1.z; As[0][aK + 7][aRow] = av1.w;
        float4 bv0 = *(const float4*)(W + (size_t)(k0 + bRow) * ldw + bn + bCol);
        float4 bv1 = *(const float4*)(W + (size_t)(k0 + bRow) * ldw + bn + bCol + 4);
        *(float4*)&Bs[0][bRow][bCol]     = bv0;
        *(float4*)&Bs[0][bRow][bCol + 4] = bv1;
    }
    __syncthreads();

    int cur = 0;
    for (int it = 0; it < iters; it++) {
        const bool has = (it + 1 < iters);
        float4 av0, av1, bv0, bv1;
        if (has) {
            const int k0 = (it0 + it + 1) * 16;
            av0 = *(const float4*)(A + (size_t)aRow * lda + k0 + aK);
            av1 = *(const float4*)(A + (size_t)aRow * lda + k0 + aK + 4);
            bv0 = *(const float4*)(W + (size_t)(k0 + bRow) * ldw + bn + bCol);
            bv1 = *(const float4*)(W + (size_t)(k0 + bRow) * ldw + bn + bCol + 4);
        }

#pragma unroll
        for (int kk = 0; kk < 16; kk++) {
            float4 a0 = *(const float4*)&As[cur][kk][mrow];
            float4 a1 = *(const float4*)&As[cur][kk][mrow + 4];
            ulonglong2 bb0 = *(const ulonglong2*)&Bs[cur][kk][ncol];
            ulonglong2 bb1 = *(const ulonglong2*)&Bs[cur][kk][ncol + 4];
            unsigned long long a2[8];
            a2[0] = pack_dup(a0.x); a2[1] = pack_dup(a0.y);
            a2[2] = pack_dup(a0.z); a2[3] = pack_dup(a0.w);
            a2[4] = pack_dup(a1.x); a2[5] = pack_dup(a1.y);
            a2[6] = pack_dup(a1.z); a2[7] = pack_dup(a1.w);
#pragma unroll
            for (int r = 0; r < 8; r++) {
                fma2(acc2[r][0], a2[r], bb0.x);
                fma2(acc2[r][1], a2[r], bb0.y);
                fma2(acc2[r][2], a2[r], bb1.x);
                fma2(acc2[r][3], a2[r], bb1.y);
            }
        }

        if (has) {
            const int nxt = cur ^ 1;
            As[nxt][aK + 0][aRow] = av0.x; As[nxt][aK + 1][aRow] = av0.y;
            As[nxt][aK + 2][aRow] = av0.z; As[nxt][aK + 3][aRow] = av0.w;
            As[nxt][aK + 4][aRow] = av1.x; As[nxt][aK + 5][aRow] = av1.y;
            As[nxt][aK + 6][aRow] = av1.z; As[nxt][aK + 7][aRow] = av1.w;
            *(float4*)&Bs[nxt][bRow][bCol]     = bv0;
            *(float4*)&Bs[nxt][bRow][bCol + 4] = bv1;
            __syncthreads();
            cur = nxt;
        }
    }

    float* __restrict__ part = g_part + (size_t)kz * OUTMN;
#pragma unroll
    for (int r = 0; r < 8; r++) {
        int m = mrow + r;
        float2 p0 = unpack2(acc2[r][0]);
        float2 p1 = unpack2(acc2[r][1]);
        float2 p2 = unpack2(acc2[r][2]);
        float2 p3 = unpack2(acc2[r][3]);
        *(float4*)(part + (size_t)m * NQKV + bn + ncol) =
            make_float4(p0.x, p0.y, p1.x, p1.y);
        *(float4*)(part + (size_t)m * NQKV + bn + ncol + 4) =
            make_float4(p2.x, p2.y, p3.x, p3.y);
    }
}

// ---------------------------------------------------------------------------
// GEMM epilogue: sum KSPLIT partials + bias + activation -> g_qkv / g_ifo
// ---------------------------------------------------------------------------
template <int MODE>
__global__ __launch_bounds__(256) void gemm_epi_kernel(const float* __restrict__ bias)
{
    const int idx = blockIdx.x * 256 + threadIdx.x;   // 0 .. OUTMN-1
    const int nn = idx % NQKV;
    float v = bias[nn];
#pragma unroll
    for (int p = 0; p < KSPLIT; p++) v += g_part[(size_t)p * OUTMN + idx];
    if (MODE == 0) {
        if (nn < 2048) v = tanhf(v);
        g_qkv[idx] = v;
    } else {
        g_ifo[idx] = 1.0f / (1.0f + expf(-v));
    }
}

// ---------------------------------------------------------------------------
// n_new = f*n + i*k ; denom[b] = max(sum_d q*n_new, 1e-6)
// ---------------------------------------------------------------------------
__global__ __launch_bounds__(256) void nnew_denom_kernel(
    const float* __restrict__ n_in, float* __restrict__ out_n)
{
    const int b = blockIdx.x;
    const int tid = threadIdx.x;
    __shared__ float red[256];

    float psum = 0.f;
#pragma unroll
    for (int d = tid; d < Hdim; d += 256) {
        float iv = g_ifo[b * NQKV + d];
        float fv = g_ifo[b * NQKV + 1024 + d];
        float kv = g_qkv[b * NQKV + 1024 + d];
        float qv = g_qkv[b * NQKV + d];
        float nn = fv * n_in[b * Hdim + d] + iv * kv;
        out_n[b * Hdim + d] = nn;
        psum += qv * nn;
    }
    red[tid] = psum;
    __syncthreads();
#pragma unroll
    for (int s = 128; s > 0; s >>= 1) {
        if (tid < s) red[tid] += red[tid + s];
        __syncthreads();
    }
    if (tid == 0) g_denom[b] = fmaxf(red[0], 1e-6f);
}

// ---------------------------------------------------------------------------
// K3: streaming C update fused with h_lin reduction — MODE-W layout.
// grid = 148 persistent blocks x 1024 threads (1 CTA/SM, 32 warps) to kill
// the cross-CTA L1tex-queue spread (B300: 32x1-warp CTAs spread 1.9x,
// 1x32-warp CTA spread 1.003).
// 1024 tiles of (b, ht): TILE_H=128 rows x 1024 cols. Thread = row-group
// (tid>>8) x col-quad (tid&255); 4 rows in flight, 32 steps per tile.
// h_lin partials reduced via smem -> g_hpart[ht][b][d] (finalize unchanged).
// ---------------------------------------------------------------------------
#define TILE_H 128

__global__ __launch_bounds__(1024, 1) void update_C_kernel(
    const float* __restrict__ C, float* __restrict__ outC)
{
    __shared__ float qs[TILE_H], fs[TILE_H], iks[TILE_H];
    __shared__ float4 sbuf[4][256];

    const int tid = threadIdx.x;
    const int rg = tid >> 8;        // row group 0..3
    const int cq = tid & 255;       // col quad 0..255
    const int ct = cq * 4;

    for (int tile = blockIdx.x; tile < Bsz * 8; tile += 148) {
        const int b  = tile >> 3;
        const int ht = tile & 7;

        __syncthreads();   // smem reuse barrier (prev tile readers done)
        if (tid < TILE_H) {
            int h = ht * TILE_H + tid;
            qs[tid]  = g_qkv[b * NQKV + h];
            float kv = g_qkv[b * NQKV + 1024 + h];
            float iv = g_ifo[b * NQKV + h];
            fs[tid]  = g_ifo[b * NQKV + 1024 + h];
            iks[tid] = iv * kv;
        }
        __syncthreads();

        const float4 v4 = *(const float4*)(g_qkv + b * NQKV + 2048 + ct);
        const size_t base = (size_t)b * Hdim * Hdim +
                            (size_t)ht * TILE_H * Hdim +
                            (size_t)rg * Hdim + ct;
        const float* __restrict__ src = C + base;
        float* __restrict__ dst = outC + base;

        float4 acc = make_float4(0.f, 0.f, 0.f, 0.f);

#pragma unroll 4
        for (int s = 0; s < 32; s++) {
            const int j = s * 4 + rg;
            float4 c4 = __ldcs((const float4*)(src + (size_t)s * 4 * Hdim));
            const float fv = fs[j], ik = iks[j], qv = qs[j];
            float4 cn;
            cn.x = fmaf(fv, c4.x, ik * v4.x);
            cn.y = fmaf(fv, c4.y, ik * v4.y);
            cn.z = fmaf(fv, c4.z, ik * v4.z);
            cn.w = fmaf(fv, c4.w, ik * v4.w);
            __stcs((float4*)(dst + (size_t)s * 4 * Hdim), cn);
            acc.x = fmaf(qv, cn.x, acc.x);
            acc.y = fmaf(qv, cn.y, acc.y);
            acc.z = fmaf(qv, cn.z, acc.z);
            acc.w = fmaf(qv, cn.w, acc.w);
        }

        sbuf[rg][cq] = acc;
        __syncthreads();
        if (tid < 256) {
            float4 s0 = sbuf[0][tid], s1 = sbuf[1][tid];
            float4 s2 = sbuf[2][tid], s3 = sbuf[3][tid];
            float4 r;
            r.x = (s0.x + s1.x) + (s2.x + s3.x);
            r.y = (s0.y + s1.y) + (s2.y + s3.y);
            r.z = (s0.z + s1.z) + (s2.z + s3.z);
            r.w = (s0.w + s1.w) + (s2.w + s3.w);
            *(float4*)(g_hpart + ht * (Bsz * Hdim) + (b << 10) + tid * 4) = r;
        }
    }
}

// ---------------------------------------------------------------------------
// K4: h_new = o * (sum_ht h_lin_part) / denom
// ---------------------------------------------------------------------------
__global__ __launch_bounds__(256) void finalize_h_kernel(float* __restrict__ out_h)
{
    const int idx = blockIdx.x * 256 + threadIdx.x;   // 131072 total
    const int b = idx >> 10;
    const int d = idx & 1023;
    float hl = 0.f;
#pragma unroll
    for (int p = 0; p < 8; p++) hl += g_hpart[p * (Bsz * Hdim) + (b << 10) + d];
    out_h[idx] = g_ifo[b * NQKV + 2048 + d] * hl / g_denom[b];
}

// ---------------------------------------------------------------------------
extern "C" void kernel_launch(void* const* d_in, const int* in_sizes, int n_in,
                              void* d_out, int out_size)
{
    // order-agnostic input resolution by element count
    const float *x = 0, *C = 0, *n_in_p = 0;
    const float *W_proj = 0, *b_proj = 0, *W_gates = 0, *b_gates = 0;

    const float* trio[3] = {0, 0, 0};
    int ntrio = 0;
    for (int idx = 0; idx < n_in; idx++) {
        const float* p = (const float*)d_in[idx];
        switch (in_sizes[idx]) {
            case 134217728: C       = p; break;
            case 4194304:   W_proj  = p; break;
            case 3145728:   W_gates = p; break;
            case 4096:      b_proj  = p; break;
            case 3072:      b_gates = p; break;
            case 131072:    if (ntrio < 3) trio[ntrio++] = p; break;
            default: break;
        }
    }
    n_in_p = trio[1];
    if (in_sizes[0] == 131072) x = trio[0];
    else                       x = trio[2];

    float* out   = (float*)d_out;
    float* out_h = out;
    float* out_C = out + Bsz * Hdim;
    float* out_n = out + Bsz * Hdim + (size_t)Bsz * Hdim * Hdim;

    dim3 ggrid(NQKV / 128, 1, KSPLIT);   // (24, 1, 6) = 144 blocks
    // K1: proj GEMM -> partials -> epi(tanh/identity) -> g_qkv
    gemm_main_kernel<0><<<ggrid, 256>>>(x, W_proj);
    gemm_epi_kernel<0><<<OUTMN / 256, 256>>>(b_proj);
    // K2: gates GEMM (A = v slice, resolved in-device) -> epi(sigmoid) -> g_ifo
    gemm_main_kernel<1><<<ggrid, 256>>>(nullptr, W_gates);
    gemm_epi_kernel<1><<<OUTMN / 256, 256>>>(b_gates);
    // n_new + denom
    nnew_denom_kernel<<<Bsz, 256>>>(n_in_p, out_n);
    // C update + fused h_lin reduction (single pass over C, mode-W)
    update_C_kernel<<<148, 1024>>>(C, out_C);
    // finalize h
    finalize_h_kernel<<<(Bsz * Hdim) / 256, 256>>>(out_h);
}

// round 12
// speedup vs baseline: 1.1730x; 1.1514x over previous
#include <cuda_runtime.h>
#include <math.h>
#include <stdint.h>

// ---------------------------------------------------------------------------
// mLSTM cell, B=128, D_IN=1024, H=1024  (SIMT + FFMA2; plain sm_103 target)
// output: concat[ h_new (128*1024), C_new (128*1024*1024), n_new (128*1024) ]
// ---------------------------------------------------------------------------

#define Bsz   128
#define Hdim  1024
#define NQKV  3072
#define KSPLIT 6
#define OUTMN (Bsz * NQKV)

__device__ float g_qkv[Bsz * NQKV];        // [b][ q | k | v ]
__device__ float g_ifo[Bsz * NQKV];        // [b][ i | f | o ]
__device__ float g_part[KSPLIT * OUTMN];
__device__ float g_hpart[8 * Bsz * Hdim];
__device__ float g_denom[Bsz];

// ---- packed f32x2 helpers ----
__device__ __forceinline__ unsigned long long pack_dup(float a) {
    unsigned long long r;
    uint32_t au = __float_as_uint(a);
    asm("mov.b64 %0, {%1, %1};" : "=l"(r) : "r"(au));
    return r;
}
__device__ __forceinline__ void fma2(unsigned long long& d,
                                     unsigned long long a,
                                     unsigned long long b) {
    asm("fma.rn.f32x2 %0, %1, %2, %0;" : "+l"(d) : "l"(a), "l"(b));
}
__device__ __forceinline__ float2 unpack2(unsigned long long v) {
    uint32_t lo, hi;
    asm("mov.b64 {%0, %1}, %2;" : "=r"(lo), "=r"(hi) : "l"(v));
    return make_float2(__uint_as_float(lo), __uint_as_float(hi));
}
__device__ __forceinline__ uint32_t smem_u32(const void* p) {
    uint32_t a;
    asm("{ .reg .u64 t; cvta.to.shared.u64 t, %1; cvt.u32.u64 %0, t; }"
        : "=r"(a) : "l"(p));
    return a;
}
__device__ __forceinline__ void cp_async16(uint32_t dst, const float* src) {
    asm volatile("cp.async.cg.shared.global [%0], [%1], 16;"
                 :: "r"(dst), "l"(src));
}

// ---------------------------------------------------------------------------
// Split-K GEMM mainloop (round-9/11 form): BM=128 BN=128 BK=16,
// 256 threads, 8x8 FFMA2 tile, double-buffered smem. grid (24,1,6).
// ---------------------------------------------------------------------------
template <int MODE>
__global__ __launch_bounds__(256) void gemm_main_kernel(
    const float* __restrict__ Aext, const float* __restrict__ W)
{
    const float* __restrict__ A = (MODE == 0) ? Aext : (const float*)(g_qkv + 2048);
    const int lda = (MODE == 0) ? 1024 : NQKV;
    const int ldw = (MODE == 0) ? 4096 : 3072;

    __shared__ float As[2][16][132];
    __shared__ float Bs[2][16][128];

    const int tid = threadIdx.x;
    const int bn = blockIdx.x * 128;
    const int kz = blockIdx.z;

    const int aRow = tid >> 1;
    const int aK   = (tid & 1) * 8;
    const int bRow = tid >> 4;
    const int bCol = (tid & 15) * 8;

    const int mrow = (tid >> 4) * 8;
    const int ncol = (tid & 15) * 8;

    unsigned long long acc2[8][4];
#pragma unroll
    for (int r = 0; r < 8; r++)
#pragma unroll
        for (int c = 0; c < 4; c++) acc2[r][c] = 0ull;

    const int it0   = kz * 10 + (kz < 4 ? kz : 4);
    const int iters = (kz < 4) ? 11 : 10;

    {
        const int k0 = it0 * 16;
        float4 av0 = *(const float4*)(A + (size_t)aRow * lda + k0 + aK);
        float4 av1 = *(const float4*)(A + (size_t)aRow * lda + k0 + aK + 4);
        As[0][aK + 0][aRow] = av0.x; As[0][aK + 1][aRow] = av0.y;
        As[0][aK + 2][aRow] = av0.z; As[0][aK + 3][aRow] = av0.w;
        As[0][aK + 4][aRow] = av1.x; As[0][aK + 5][aRow] = av1.y;
        As[0][aK + 6][aRow] = av1.z; As[0][aK + 7][aRow] = av1.w;
        float4 bv0 = *(const float4*)(W + (size_t)(k0 + bRow) * ldw + bn + bCol);
        float4 bv1 = *(const float4*)(W + (size_t)(k0 + bRow) * ldw + bn + bCol + 4);
        *(float4*)&Bs[0][bRow][bCol]     = bv0;
        *(float4*)&Bs[0][bRow][bCol + 4] = bv1;
    }
    __syncthreads();

    int cur = 0;
    for (int it = 0; it < iters; it++) {
        const bool has = (it + 1 < iters);
        float4 av0, av1, bv0, bv1;
        if (has) {
            const int k0 = (it0 + it + 1) * 16;
            av0 = *(const float4*)(A + (size_t)aRow * lda + k0 + aK);
            av1 = *(const float4*)(A + (size_t)aRow * lda + k0 + aK + 4);
            bv0 = *(const float4*)(W + (size_t)(k0 + bRow) * ldw + bn + bCol);
            bv1 = *(const float4*)(W + (size_t)(k0 + bRow) * ldw + bn + bCol + 4);
        }

#pragma unroll
        for (int kk = 0; kk < 16; kk++) {
            float4 a0 = *(const float4*)&As[cur][kk][mrow];
            float4 a1 = *(const float4*)&As[cur][kk][mrow + 4];
            ulonglong2 bb0 = *(const ulonglong2*)&Bs[cur][kk][ncol];
            ulonglong2 bb1 = *(const ulonglong2*)&Bs[cur][kk][ncol + 4];
            unsigned long long a2[8];
            a2[0] = pack_dup(a0.x); a2[1] = pack_dup(a0.y);
            a2[2] = pack_dup(a0.z); a2[3] = pack_dup(a0.w);
            a2[4] = pack_dup(a1.x); a2[5] = pack_dup(a1.y);
            a2[6] = pack_dup(a1.z); a2[7] = pack_dup(a1.w);
#pragma unroll
            for (int r = 0; r < 8; r++) {
                fma2(acc2[r][0], a2[r], bb0.x);
                fma2(acc2[r][1], a2[r], bb0.y);
                fma2(acc2[r][2], a2[r], bb1.x);
                fma2(acc2[r][3], a2[r], bb1.y);
            }
        }

        if (has) {
            const int nxt = cur ^ 1;
            As[nxt][aK + 0][aRow] = av0.x; As[nxt][aK + 1][aRow] = av0.y;
            As[nxt][aK + 2][aRow] = av0.z; As[nxt][aK + 3][aRow] = av0.w;
            As[nxt][aK + 4][aRow] = av1.x; As[nxt][aK + 5][aRow] = av1.y;
            As[nxt][aK + 6][aRow] = av1.z; As[nxt][aK + 7][aRow] = av1.w;
            *(float4*)&Bs[nxt][bRow][bCol]     = bv0;
            *(float4*)&Bs[nxt][bRow][bCol + 4] = bv1;
            __syncthreads();
            cur = nxt;
        }
    }

    float* __restrict__ part = g_part + (size_t)kz * OUTMN;
#pragma unroll
    for (int r = 0; r < 8; r++) {
        int m = mrow + r;
        float2 p0 = unpack2(acc2[r][0]);
        float2 p1 = unpack2(acc2[r][1]);
        float2 p2 = unpack2(acc2[r][2]);
        float2 p3 = unpack2(acc2[r][3]);
        *(float4*)(part + (size_t)m * NQKV + bn + ncol) =
            make_float4(p0.x, p0.y, p1.x, p1.y);
        *(float4*)(part + (size_t)m * NQKV + bn + ncol + 4) =
            make_float4(p2.x, p2.y, p3.x, p3.y);
    }
}

// ---------------------------------------------------------------------------
// GEMM epilogue
// ---------------------------------------------------------------------------
template <int MODE>
__global__ __launch_bounds__(256) void gemm_epi_kernel(const float* __restrict__ bias)
{
    const int idx = blockIdx.x * 256 + threadIdx.x;
    const int nn = idx % NQKV;
    float v = bias[nn];
#pragma unroll
    for (int p = 0; p < KSPLIT; p++) v += g_part[(size_t)p * OUTMN + idx];
    if (MODE == 0) {
        if (nn < 2048) v = tanhf(v);
        g_qkv[idx] = v;
    } else {
        g_ifo[idx] = 1.0f / (1.0f + expf(-v));
    }
}

// ---------------------------------------------------------------------------
// n_new + denom
// ---------------------------------------------------------------------------
__global__ __launch_bounds__(256) void nnew_denom_kernel(
    const float* __restrict__ n_in, float* __restrict__ out_n)
{
    const int b = blockIdx.x;
    const int tid = threadIdx.x;
    __shared__ float red[256];

    float psum = 0.f;
#pragma unroll
    for (int d = tid; d < Hdim; d += 256) {
        float iv = g_ifo[b * NQKV + d];
        float fv = g_ifo[b * NQKV + 1024 + d];
        float kv = g_qkv[b * NQKV + 1024 + d];
        float qv = g_qkv[b * NQKV + d];
        float nn = fv * n_in[b * Hdim + d] + iv * kv;
        out_n[b * Hdim + d] = nn;
        psum += qv * nn;
    }
    red[tid] = psum;
    __syncthreads();
#pragma unroll
    for (int s = 128; s > 0; s >>= 1) {
        if (tid < s) red[tid] += red[tid + s];
        __syncthreads();
    }
    if (tid == 0) g_denom[b] = fmaxf(red[0], 1e-6f);
}

// ---------------------------------------------------------------------------
// K3: C update + fused h_lin, cp.async-staged chunks.
// 148 persistent CTAs x 1024 threads. Tile = (b, ht): 128 rows x 1024 cols.
// Tile processed as 8 chunks of 16 rows (64KB), double-buffered in smem:
//   read phase  = cp.async.cg bulk burst (C -> smem, register-free)
//   write phase = compute from smem, STG.128 streaming stores only
// This decouples the DRAM read stream from the write stream (coarse bursts)
// instead of per-warp read/write alternation.
// Dynamic smem: 2 x 64KB.
// ---------------------------------------------------------------------------
#define HH (Hdim * Hdim)

__global__ __launch_bounds__(1024, 1) void update_C_kernel(
    const float* __restrict__ C, float* __restrict__ outC)
{
    extern __shared__ float dynbuf[];          // [2][16][1024]
    __shared__ float qs[128], fs[128], iks[128];
    __shared__ float4 sbuf[4][256];

    const int tid = threadIdx.x;
    const int rg = tid >> 8;        // 0..3
    const int cq = tid & 255;       // 0..255
    const int ct = cq * 4;
    const uint32_t sbase = smem_u32(dynbuf);

    for (int tile = blockIdx.x; tile < Bsz * 8; tile += 148) {
        const int b  = tile >> 3;
        const int ht = tile & 7;

        __syncthreads();   // previous tile fully consumed (smem reuse)
        if (tid < 128) {
            int h = ht * 128 + tid;
            qs[tid]  = g_qkv[b * NQKV + h];
            float kv = g_qkv[b * NQKV + 1024 + h];
            float iv = g_ifo[b * NQKV + h];
            fs[tid]  = g_ifo[b * NQKV + 1024 + h];
            iks[tid] = iv * kv;
        }

        const float* __restrict__ srcT = C   + (size_t)b * HH + (size_t)ht * 128 * Hdim;
        float* __restrict__       dstT = outC + (size_t)b * HH + (size_t)ht * 128 * Hdim;

        // issue chunk 0 into buffer 0 (rows 0..15)
#pragma unroll
        for (int r = 0; r < 4; r++) {
            int jj = r * 4 + rg;
            cp_async16(sbase + (uint32_t)(jj * 1024 + ct) * 4,
                       srcT + (size_t)jj * Hdim + ct);
        }
        asm volatile("cp.async.commit_group;");
        __syncthreads();   // qs/fs/iks visible

        const float4 v4 = *(const float4*)(g_qkv + b * NQKV + 2048 + ct);
        float4 acc = make_float4(0.f, 0.f, 0.f, 0.f);

        for (int c = 0; c < 8; c++) {
            if (c < 7) {
                const float* s2 = srcT + (size_t)(c + 1) * 16 * Hdim;
                uint32_t d2 = sbase + (uint32_t)(((c + 1) & 1) * 65536);
#pragma unroll
                for (int r = 0; r < 4; r++) {
                    int jj = r * 4 + rg;
                    cp_async16(d2 + (uint32_t)(jj * 1024 + ct) * 4,
                               s2 + (size_t)jj * Hdim + ct);
                }
                asm volatile("cp.async.commit_group;");
                asm volatile("cp.async.wait_group 1;");   // chunk c arrived
            } else {
                asm volatile("cp.async.wait_group 0;");
            }
            __syncthreads();

            const float* buf = dynbuf + (c & 1) * 16384;
            float* __restrict__ dstC = dstT + (size_t)c * 16 * Hdim;
#pragma unroll
            for (int s = 0; s < 4; s++) {
                int jj = s * 4 + rg;
                int j  = c * 16 + jj;
                float4 c4 = *(const float4*)(buf + jj * 1024 + ct);
                const float fv = fs[j], ik = iks[j], qv = qs[j];
                float4 cn;
                cn.x = fmaf(fv, c4.x, ik * v4.x);
                cn.y = fmaf(fv, c4.y, ik * v4.y);
                cn.z = fmaf(fv, c4.z, ik * v4.z);
                cn.w = fmaf(fv, c4.w, ik * v4.w);
                __stcs((float4*)(dstC + (size_t)jj * Hdim + ct), cn);
                acc.x = fmaf(qv, cn.x, acc.x);
                acc.y = fmaf(qv, cn.y, acc.y);
                acc.z = fmaf(qv, cn.z, acc.z);
                acc.w = fmaf(qv, cn.w, acc.w);
            }
            __syncthreads();   // readers done before buffer is overwritten
        }

        sbuf[rg][cq] = acc;
        __syncthreads();
        if (tid < 256) {
            float4 s0 = sbuf[0][tid], s1 = sbuf[1][tid];
            float4 s2 = sbuf[2][tid], s3 = sbuf[3][tid];
            float4 r;
            r.x = (s0.x + s1.x) + (s2.x + s3.x);
            r.y = (s0.y + s1.y) + (s2.y + s3.y);
            r.z = (s0.z + s1.z) + (s2.z + s3.z);
            r.w = (s0.w + s1.w) + (s2.w + s3.w);
            *(float4*)(g_hpart + ht * (Bsz * Hdim) + (b << 10) + tid * 4) = r;
        }
    }
}

// ---------------------------------------------------------------------------
// K4: h_new = o * (sum_ht h_lin_part) / denom
// ---------------------------------------------------------------------------
__global__ __launch_bounds__(256) void finalize_h_kernel(float* __restrict__ out_h)
{
    const int idx = blockIdx.x * 256 + threadIdx.x;
    const int b = idx >> 10;
    const int d = idx & 1023;
    float hl = 0.f;
#pragma unroll
    for (int p = 0; p < 8; p++) hl += g_hpart[p * (Bsz * Hdim) + (b << 10) + d];
    out_h[idx] = g_ifo[b * NQKV + 2048 + d] * hl / g_denom[b];
}

// ---------------------------------------------------------------------------
extern "C" void kernel_launch(void* const* d_in, const int* in_sizes, int n_in,
                              void* d_out, int out_size)
{
    const float *x = 0, *C = 0, *n_in_p = 0;
    const float *W_proj = 0, *b_proj = 0, *W_gates = 0, *b_gates = 0;

    const float* trio[3] = {0, 0, 0};
    int ntrio = 0;
    for (int idx = 0; idx < n_in; idx++) {
        const float* p = (const float*)d_in[idx];
        switch (in_sizes[idx]) {
            case 134217728: C       = p; break;
            case 4194304:   W_proj  = p; break;
            case 3145728:   W_gates = p; break;
            case 4096:      b_proj  = p; break;
            case 3072:      b_gates = p; break;
            case 131072:    if (ntrio < 3) trio[ntrio++] = p; break;
            default: break;
        }
    }
    n_in_p = trio[1];
    if (in_sizes[0] == 131072) x = trio[0];
    else                       x = trio[2];

    float* out   = (float*)d_out;
    float* out_h = out;
    float* out_C = out + Bsz * Hdim;
    float* out_n = out + Bsz * Hdim + (size_t)Bsz * Hdim * Hdim;

    cudaFuncSetAttribute(update_C_kernel,
                         cudaFuncAttributeMaxDynamicSharedMemorySize, 131072);

    dim3 ggrid(NQKV / 128, 1, KSPLIT);   // (24, 1, 6)
    gemm_main_kernel<0><<<ggrid, 256>>>(x, W_proj);
    gemm_epi_kernel<0><<<OUTMN / 256, 256>>>(b_proj);
    gemm_main_kernel<1><<<ggrid, 256>>>(nullptr, W_gates);
    gemm_epi_kernel<1><<<OUTMN / 256, 256>>>(b_gates);
    nnew_denom_kernel<<<Bsz, 256>>>(n_in_p, out_n);
    update_C_kernel<<<148, 1024, 131072>>>(C, out_C);
    finalize_h_kernel<<<(Bsz * Hdim) / 256, 256>>>(out_h);
}